// round 1
// baseline (speedup 1.0000x reference)
#include <cuda_runtime.h>
#include <math.h>

#define DIMS   768
#define HEADS  8
#define HD     96
#define SEQL   2048
#define BATCH  2
#define NROWS  (BATCH*SEQL)   // 4096

// ---------------------------------------------------------------------------
// Scratch (static device globals: allocation-free, graph-capture safe)
// ---------------------------------------------------------------------------
__device__ float g_q  [NROWS*DIMS];
__device__ float g_k  [NROWS*DIMS];
__device__ float g_v  [NROWS*DIMS];
__device__ float g_att[NROWS*DIMS];

// ---------------------------------------------------------------------------
// Generic NT GEMM:  C[M,N] = A[M,K] * B[N,K]^T   (both operands K-major)
// Tile 128x64, BK=16, 128 threads, 8x8 micro-tile per thread.
// Column ownership stride-8 (col = 8c+tx): conflict-free sB reads, coalesced C.
// ---------------------------------------------------------------------------
#define GBM 128
#define GBN 64
#define GBK 16

__global__ __launch_bounds__(128)
void gemm_nt_kernel(const float* __restrict__ A, const float* __restrict__ Bm,
                    float* __restrict__ C, int M, int N, int K)
{
    __shared__ float sA[GBM][GBK + 1];
    __shared__ float sB[GBN][GBK + 1];

    const int tid = threadIdx.x;
    const int tx  = tid & 7;      // 0..7
    const int ty  = tid >> 3;     // 0..15
    const int rowBase = blockIdx.x * GBM;
    const int colBase = blockIdx.y * GBN;

    float acc[8][8];
#pragma unroll
    for (int r = 0; r < 8; r++)
#pragma unroll
        for (int c = 0; c < 8; c++) acc[r][c] = 0.f;

    for (int k0 = 0; k0 < K; k0 += GBK) {
        // fill A tile: 128*16 = 2048 elems, 16 per thread
#pragma unroll
        for (int i = 0; i < (GBM * GBK) / 128; i++) {
            int idx = tid + i * 128;
            int r = idx / GBK, c = idx % GBK;
            sA[r][c] = A[(size_t)(rowBase + r) * K + k0 + c];
        }
        // fill B tile: 64*16 = 1024 elems, 8 per thread
#pragma unroll
        for (int i = 0; i < (GBN * GBK) / 128; i++) {
            int idx = tid + i * 128;
            int r = idx / GBK, c = idx % GBK;
            sB[r][c] = Bm[(size_t)(colBase + r) * K + k0 + c];
        }
        __syncthreads();

#pragma unroll
        for (int k = 0; k < GBK; k++) {
            float a[8], b[8];
#pragma unroll
            for (int r = 0; r < 8; r++) a[r] = sA[ty * 8 + r][k];
#pragma unroll
            for (int c = 0; c < 8; c++) b[c] = sB[c * 8 + tx][k];
#pragma unroll
            for (int r = 0; r < 8; r++)
#pragma unroll
                for (int c = 0; c < 8; c++)
                    acc[r][c] = fmaf(a[r], b[c], acc[r][c]);
        }
        __syncthreads();
    }

#pragma unroll
    for (int r = 0; r < 8; r++) {
        size_t rowOff = (size_t)(rowBase + ty * 8 + r) * N + colBase;
#pragma unroll
        for (int c = 0; c < 8; c++)
            C[rowOff + c * 8 + tx] = acc[r][c];
    }
}

// ---------------------------------------------------------------------------
// 3D-coordinate RoPE, in place on [B, L, HEADS*HD] with per-head layout.
// One thread per (b,l,h,pair); pair p -> axis = p/16, j = p%16.
// x1 = x[axis*32 + j], x2 = x[axis*32 + 16 + j]
// ---------------------------------------------------------------------------
__global__ void rope_kernel(float* __restrict__ x, const float* __restrict__ coords)
{
    const int total = NROWS * HEADS * 48;
    int idx = blockIdx.x * blockDim.x + threadIdx.x;
    if (idx >= total) return;

    int p  = idx % 48;
    int h  = (idx / 48) % HEADS;
    int bl = idx / (48 * HEADS);          // b*L + l
    int axis = p >> 4;                    // 0..2
    int j    = p & 15;                    // 0..15

    float coord = coords[(size_t)bl * 3 + axis];
    // inv_freq = 10000^(-j/16)
    float inv = expf(-(float)j * (1.0f / 16.0f) * logf(10000.0f));
    float ang = coord * inv;
    float s, c;
    sincosf(ang, &s, &c);

    float* base = x + (size_t)bl * DIMS + h * HD + axis * 32;
    float x1 = base[j];
    float x2 = base[j + 16];
    base[j]      = x1 * c - x2 * s;
    base[j + 16] = x1 * s + x2 * c;
}

// ---------------------------------------------------------------------------
// Flash attention, fp32, online softmax.
// Grid: (L/64, HEADS, BATCH). Block: 128 threads (tx = tid&7, ty = tid>>3).
// Per-thread: 4 query rows (4*ty+r), 8 S-cols (8c+tx), 12 O-cols (8c+tx).
// smem: sQ[64][97], sK[64][97], sV[64][97], sP[64][65]  (~91 KB dynamic)
// ---------------------------------------------------------------------------
#define ABM 64
#define ABN 64
#define QS  97
#define PS  65
#define ATTN_SMEM_BYTES ((3 * ABM * QS + ABM * PS) * (int)sizeof(float))

__global__ __launch_bounds__(128)
void attn_kernel(const float* __restrict__ Q, const float* __restrict__ K,
                 const float* __restrict__ V, float* __restrict__ O)
{
    extern __shared__ float smem[];
    float* sQ = smem;
    float* sK = sQ + ABM * QS;
    float* sV = sK + ABN * QS;
    float* sP = sV + ABN * QS;

    const int tid = threadIdx.x;
    const int tx  = tid & 7;
    const int ty  = tid >> 3;
    const int tile = blockIdx.x;
    const int h    = blockIdx.y;
    const int b    = blockIdx.z;
    const int q0   = tile * ABM;

    const float scale = rsqrtf((float)HD);

    const float* Qb = Q + (size_t)b * SEQL * DIMS + h * HD;
    const float* Kb = K + (size_t)b * SEQL * DIMS + h * HD;
    const float* Vb = V + (size_t)b * SEQL * DIMS + h * HD;

    // load Q tile [64, 96]
    for (int i = tid; i < ABM * HD; i += 128) {
        int r = i / HD, c = i % HD;
        sQ[r * QS + c] = Qb[(size_t)(q0 + r) * DIMS + c];
    }

    float o[4][12];
    float m[4], l[4];
#pragma unroll
    for (int r = 0; r < 4; r++) {
        m[r] = -1e30f; l[r] = 0.f;
#pragma unroll
        for (int c = 0; c < 12; c++) o[r][c] = 0.f;
    }

    for (int k0 = 0; k0 < SEQL; k0 += ABN) {
        __syncthreads();   // prev iter done with sK/sV/sP; first iter: sQ ready
        // load K and V tiles [64, 96]
        for (int i = tid; i < ABN * HD; i += 128) {
            int r = i / HD, c = i % HD;
            sK[r * QS + c] = Kb[(size_t)(k0 + r) * DIMS + c];
            sV[r * QS + c] = Vb[(size_t)(k0 + r) * DIMS + c];
        }
        __syncthreads();

        // S = Q K^T   (4 rows x 8 cols per thread; col = 8c+tx)
        float s[4][8];
#pragma unroll
        for (int r = 0; r < 4; r++)
#pragma unroll
            for (int c = 0; c < 8; c++) s[r][c] = 0.f;

#pragma unroll 2
        for (int d = 0; d < HD; d++) {
            float qv[4], kv[8];
#pragma unroll
            for (int r = 0; r < 4; r++) qv[r] = sQ[(4 * ty + r) * QS + d];
#pragma unroll
            for (int c = 0; c < 8; c++) kv[c] = sK[(8 * c + tx) * QS + d];
#pragma unroll
            for (int r = 0; r < 4; r++)
#pragma unroll
                for (int c = 0; c < 8; c++)
                    s[r][c] = fmaf(qv[r], kv[c], s[r][c]);
        }

        // online softmax per row
#pragma unroll
        for (int r = 0; r < 4; r++) {
            float mt = -1e30f;
#pragma unroll
            for (int c = 0; c < 8; c++) {
                s[r][c] *= scale;
                mt = fmaxf(mt, s[r][c]);
            }
#pragma unroll
            for (int w = 1; w < 8; w <<= 1)
                mt = fmaxf(mt, __shfl_xor_sync(0xffffffffu, mt, w));
            float mnew  = fmaxf(m[r], mt);
            float alpha = __expf(m[r] - mnew);
            float lsum  = 0.f;
#pragma unroll
            for (int c = 0; c < 8; c++) {
                float p = __expf(s[r][c] - mnew);
                sP[(4 * ty + r) * PS + 8 * c + tx] = p;
                lsum += p;
            }
#pragma unroll
            for (int w = 1; w < 8; w <<= 1)
                lsum += __shfl_xor_sync(0xffffffffu, lsum, w);
            l[r] = l[r] * alpha + lsum;
            m[r] = mnew;
#pragma unroll
            for (int c = 0; c < 12; c++) o[r][c] *= alpha;
        }
        __syncthreads();

        // O += P V   (12 O-cols per thread; col = 8c+tx)
#pragma unroll 2
        for (int j = 0; j < ABN; j++) {
            float pv[4], vv[12];
#pragma unroll
            for (int r = 0; r < 4; r++) pv[r] = sP[(4 * ty + r) * PS + j];
#pragma unroll
            for (int c = 0; c < 12; c++) vv[c] = sV[j * QS + 8 * c + tx];
#pragma unroll
            for (int r = 0; r < 4; r++)
#pragma unroll
                for (int c = 0; c < 12; c++)
                    o[r][c] = fmaf(pv[r], vv[c], o[r][c]);
        }
    }

    // epilogue: normalize + store into [b, l, h*HD + col]
#pragma unroll
    for (int r = 0; r < 4; r++) {
        float inv = 1.f / l[r];
        size_t rowOff = (size_t)(b * SEQL + q0 + 4 * ty + r) * DIMS + h * HD;
#pragma unroll
        for (int c = 0; c < 12; c++)
            O[rowOff + 8 * c + tx] = o[r][c] * inv;
    }
}

// ---------------------------------------------------------------------------
// Launch
// ---------------------------------------------------------------------------
extern "C" void kernel_launch(void* const* d_in, const int* in_sizes, int n_in,
                              void* d_out, int out_size)
{
    const float* Q_in = (const float*)d_in[0];
    const float* K_in = (const float*)d_in[1];
    const float* V_in = (const float*)d_in[2];
    const float* cq   = (const float*)d_in[3];
    const float* ck   = (const float*)d_in[4];
    const float* Wq   = (const float*)d_in[5];
    const float* Wk   = (const float*)d_in[6];
    const float* Wv   = (const float*)d_in[7];
    const float* Wo   = (const float*)d_in[8];
    float* out = (float*)d_out;

    float *q, *k, *v, *att;
    cudaGetSymbolAddress((void**)&q,   g_q);
    cudaGetSymbolAddress((void**)&k,   g_k);
    cudaGetSymbolAddress((void**)&v,   g_v);
    cudaGetSymbolAddress((void**)&att, g_att);

    dim3 gemmGrid(NROWS / GBM, DIMS / GBN);   // 32 x 12

    // projections
    gemm_nt_kernel<<<gemmGrid, 128>>>(Q_in, Wq, q, NROWS, DIMS, DIMS);
    gemm_nt_kernel<<<gemmGrid, 128>>>(K_in, Wk, k, NROWS, DIMS, DIMS);
    gemm_nt_kernel<<<gemmGrid, 128>>>(V_in, Wv, v, NROWS, DIMS, DIMS);

    // RoPE on q, k
    {
        int total  = NROWS * HEADS * 48;
        int blocks = (total + 255) / 256;
        rope_kernel<<<blocks, 256>>>(q, cq);
        rope_kernel<<<blocks, 256>>>(k, ck);
    }

    // flash attention
    cudaFuncSetAttribute(attn_kernel, cudaFuncAttributeMaxDynamicSharedMemorySize,
                         ATTN_SMEM_BYTES);
    attn_kernel<<<dim3(SEQL / ABM, HEADS, BATCH), 128, ATTN_SMEM_BYTES>>>(q, k, v, att);

    // output projection -> d_out
    gemm_nt_kernel<<<gemmGrid, 128>>>(att, Wo, out, NROWS, DIMS, DIMS);
}

// round 3
// speedup vs baseline: 1.2643x; 1.2643x over previous
#include <cuda_runtime.h>
#include <math.h>
#include <stdint.h>

#define DIMS   768
#define HEADS  8
#define HD     96
#define SEQL   2048
#define BATCH  2
#define NROWS  (BATCH*SEQL)   // 4096

// ---------------------------------------------------------------------------
// Scratch (static device globals: allocation-free, graph-capture safe)
// ---------------------------------------------------------------------------
__device__ float g_q  [NROWS*DIMS];
__device__ float g_k  [NROWS*DIMS];
__device__ float g_v  [NROWS*DIMS];
__device__ float g_att[NROWS*DIMS];

// ---------------------------------------------------------------------------
// PTX helpers
// ---------------------------------------------------------------------------
__device__ __forceinline__ uint32_t smem_u32(const void* p) {
    uint32_t a;
    asm("{ .reg .u64 t; cvta.to.shared.u64 t, %1; cvt.u32.u64 %0, t; }" : "=r"(a) : "l"(p));
    return a;
}
__device__ __forceinline__ void cp_async16(uint32_t dst, const void* src) {
    asm volatile("cp.async.cg.shared.global [%0], [%1], 16;" :: "r"(dst), "l"(src));
}
__device__ __forceinline__ void cp_async_commit() { asm volatile("cp.async.commit_group;" ::: "memory"); }
template<int N>
__device__ __forceinline__ void cp_async_wait() { asm volatile("cp.async.wait_group %0;" :: "n"(N) : "memory"); }

__device__ __forceinline__ uint32_t f2tf32(float x) {
    uint32_t u;
    asm("cvt.rna.tf32.f32 %0, %1;" : "=r"(u) : "f"(x));
    return u;
}
__device__ __forceinline__ void mma_tf32(float& c0, float& c1, float& c2, float& c3,
                                         uint32_t a0, uint32_t a1, uint32_t a2, uint32_t a3,
                                         uint32_t b0, uint32_t b1) {
    asm volatile(
        "mma.sync.aligned.m16n8k8.row.col.f32.tf32.tf32.f32 "
        "{%0,%1,%2,%3}, {%4,%5,%6,%7}, {%8,%9}, {%0,%1,%2,%3};"
        : "+f"(c0), "+f"(c1), "+f"(c2), "+f"(c3)
        : "r"(a0), "r"(a1), "r"(a2), "r"(a3), "r"(b0), "r"(b1));
}

// ---------------------------------------------------------------------------
// Tensor-core NT GEMM via legacy mma.sync (tf32):
//   C[M,N] = A[M,K] * B[N,K]^T, fp32 in / tf32 MMA / fp32 out
// CTA tile 128x128, 256 threads (8 warps, 4x2), warp tile 32x64.
// K streamed in 32-float chunks through a 2-stage cp.async pipeline.
// smem per tile row pitch = 36 floats (conflict-free fragment loads).
// ---------------------------------------------------------------------------
#define TM   128
#define TN   128
#define KCH  32
#define PITCH 36
#define STAGE_F (TM * PITCH)                    // floats per stage per operand
#define GEMM_SMEM_BYTES (4 * STAGE_F * 4)       // 2 stages x (A+B) = 73728 B

__global__ __launch_bounds__(256)
void gemm_mma_kernel(const float* __restrict__ A, const float* __restrict__ B,
                     float* __restrict__ C, int M, int N, int K)
{
    extern __shared__ float smem[];
    float* sA = smem;                  // [2][128][36]
    float* sB = smem + 2 * STAGE_F;    // [2][128][36]

    const int tid  = threadIdx.x;
    const int wid  = tid >> 5;
    const int lane = tid & 31;
    const int grp  = lane >> 2;        // 0..7
    const int thr  = lane & 3;         // 0..3
    const int wm   = (wid & 3) * 32;   // warp row offset in CTA tile
    const int wn   = (wid >> 2) * 64;  // warp col offset
    const int rowBase = blockIdx.x * TM;
    const int colBase = blockIdx.y * TN;

    const uint32_t sA_u = smem_u32(sA);
    const uint32_t sB_u = smem_u32(sB);

    float acc[2][8][4];
#pragma unroll
    for (int mt = 0; mt < 2; mt++)
#pragma unroll
        for (int nt = 0; nt < 8; nt++)
#pragma unroll
            for (int i = 0; i < 4; i++) acc[mt][nt][i] = 0.f;

    const int nChunks = K / KCH;       // 24

    // prefetch helper (done inline twice to keep addressing simple)
#define PREFETCH(ch)                                                            \
    do {                                                                        \
        int _k0 = (ch) * KCH;                                                   \
        uint32_t _dA = sA_u + ((ch) & 1) * STAGE_F * 4;                         \
        uint32_t _dB = sB_u + ((ch) & 1) * STAGE_F * 4;                         \
        _Pragma("unroll")                                                       \
        for (int _it = 0; _it < 4; _it++) {                                     \
            int _idx = tid + _it * 256;                                         \
            int _r = _idx >> 3, _seg = _idx & 7;                                \
            cp_async16(_dA + (_r * PITCH + _seg * 4) * 4,                       \
                       A + (size_t)(rowBase + _r) * K + _k0 + _seg * 4);        \
            cp_async16(_dB + (_r * PITCH + _seg * 4) * 4,                       \
                       B + (size_t)(colBase + _r) * K + _k0 + _seg * 4);        \
        }                                                                       \
        cp_async_commit();                                                      \
    } while (0)

    PREFETCH(0);

    for (int ch = 0; ch < nChunks; ch++) {
        if (ch + 1 < nChunks) {
            PREFETCH(ch + 1);
            cp_async_wait<1>();
        } else {
            cp_async_wait<0>();
        }
        __syncthreads();

        const float* cA = sA + (ch & 1) * STAGE_F;
        const float* cB = sB + (ch & 1) * STAGE_F;

#pragma unroll
        for (int ks = 0; ks < 4; ks++) {
            const int kk = ks * 8;
            // A fragments: 2 m16 tiles x 4 regs
            uint32_t af[2][4];
#pragma unroll
            for (int mt = 0; mt < 2; mt++) {
                int rb = wm + mt * 16 + grp;
                af[mt][0] = f2tf32(cA[(rb    ) * PITCH + kk + thr    ]);
                af[mt][1] = f2tf32(cA[(rb + 8) * PITCH + kk + thr    ]);
                af[mt][2] = f2tf32(cA[(rb    ) * PITCH + kk + thr + 4]);
                af[mt][3] = f2tf32(cA[(rb + 8) * PITCH + kk + thr + 4]);
            }
            // B fragments: 8 n8 tiles x 2 regs
            uint32_t bf[8][2];
#pragma unroll
            for (int nt = 0; nt < 8; nt++) {
                int cb = wn + nt * 8 + grp;
                bf[nt][0] = f2tf32(cB[cb * PITCH + kk + thr    ]);
                bf[nt][1] = f2tf32(cB[cb * PITCH + kk + thr + 4]);
            }
#pragma unroll
            for (int mt = 0; mt < 2; mt++)
#pragma unroll
                for (int nt = 0; nt < 8; nt++)
                    mma_tf32(acc[mt][nt][0], acc[mt][nt][1],
                             acc[mt][nt][2], acc[mt][nt][3],
                             af[mt][0], af[mt][1], af[mt][2], af[mt][3],
                             bf[nt][0], bf[nt][1]);
        }
        __syncthreads();
    }
#undef PREFETCH

    // Epilogue: direct v2 stores. c0/c1 -> (row, col..col+1), c2/c3 -> row+8.
#pragma unroll
    for (int mt = 0; mt < 2; mt++) {
        int r0 = rowBase + wm + mt * 16 + grp;
#pragma unroll
        for (int nt = 0; nt < 8; nt++) {
            int c0 = colBase + wn + nt * 8 + thr * 2;
            float2* p0 = (float2*)(C + (size_t)r0 * N + c0);
            float2* p1 = (float2*)(C + (size_t)(r0 + 8) * N + c0);
            *p0 = make_float2(acc[mt][nt][0], acc[mt][nt][1]);
            *p1 = make_float2(acc[mt][nt][2], acc[mt][nt][3]);
        }
    }
}

// ---------------------------------------------------------------------------
// 3D-coordinate RoPE (unchanged)
// ---------------------------------------------------------------------------
__global__ void rope_kernel(float* __restrict__ x, const float* __restrict__ coords)
{
    const int total = NROWS * HEADS * 48;
    int idx = blockIdx.x * blockDim.x + threadIdx.x;
    if (idx >= total) return;

    int p  = idx % 48;
    int h  = (idx / 48) % HEADS;
    int bl = idx / (48 * HEADS);
    int axis = p >> 4;
    int j    = p & 15;

    float coord = coords[(size_t)bl * 3 + axis];
    float inv = expf(-(float)j * (1.0f / 16.0f) * logf(10000.0f));
    float ang = coord * inv;
    float s, c;
    sincosf(ang, &s, &c);

    float* base = x + (size_t)bl * DIMS + h * HD + axis * 32;
    float x1 = base[j];
    float x2 = base[j + 16];
    base[j]      = x1 * c - x2 * s;
    base[j + 16] = x1 * s + x2 * c;
}

// ---------------------------------------------------------------------------
// Flash attention, fp32 (unchanged from R1)
// ---------------------------------------------------------------------------
#define ABM 64
#define ABN 64
#define QS  97
#define PS  65
#define ATTN_SMEM_BYTES ((3 * ABM * QS + ABM * PS) * (int)sizeof(float))

__global__ __launch_bounds__(128)
void attn_kernel(const float* __restrict__ Q, const float* __restrict__ K,
                 const float* __restrict__ V, float* __restrict__ O)
{
    extern __shared__ float smem[];
    float* sQ = smem;
    float* sK = sQ + ABM * QS;
    float* sV = sK + ABN * QS;
    float* sP = sV + ABN * QS;

    const int tid = threadIdx.x;
    const int tx  = tid & 7;
    const int ty  = tid >> 3;
    const int q0  = blockIdx.x * ABM;
    const int h   = blockIdx.y;
    const int b   = blockIdx.z;

    const float scale = rsqrtf((float)HD);

    const float* Qb = Q + (size_t)b * SEQL * DIMS + h * HD;
    const float* Kb = K + (size_t)b * SEQL * DIMS + h * HD;
    const float* Vb = V + (size_t)b * SEQL * DIMS + h * HD;

    for (int i = tid; i < ABM * HD; i += 128) {
        int r = i / HD, c = i % HD;
        sQ[r * QS + c] = Qb[(size_t)(q0 + r) * DIMS + c];
    }

    float o[4][12];
    float m[4], l[4];
#pragma unroll
    for (int r = 0; r < 4; r++) {
        m[r] = -1e30f; l[r] = 0.f;
#pragma unroll
        for (int c = 0; c < 12; c++) o[r][c] = 0.f;
    }

    for (int k0 = 0; k0 < SEQL; k0 += ABN) {
        __syncthreads();
        for (int i = tid; i < ABN * HD; i += 128) {
            int r = i / HD, c = i % HD;
            sK[r * QS + c] = Kb[(size_t)(k0 + r) * DIMS + c];
            sV[r * QS + c] = Vb[(size_t)(k0 + r) * DIMS + c];
        }
        __syncthreads();

        float s[4][8];
#pragma unroll
        for (int r = 0; r < 4; r++)
#pragma unroll
            for (int c = 0; c < 8; c++) s[r][c] = 0.f;

#pragma unroll 2
        for (int d = 0; d < HD; d++) {
            float qv[4], kv[8];
#pragma unroll
            for (int r = 0; r < 4; r++) qv[r] = sQ[(4 * ty + r) * QS + d];
#pragma unroll
            for (int c = 0; c < 8; c++) kv[c] = sK[(8 * c + tx) * QS + d];
#pragma unroll
            for (int r = 0; r < 4; r++)
#pragma unroll
                for (int c = 0; c < 8; c++)
                    s[r][c] = fmaf(qv[r], kv[c], s[r][c]);
        }

#pragma unroll
        for (int r = 0; r < 4; r++) {
            float mt = -1e30f;
#pragma unroll
            for (int c = 0; c < 8; c++) {
                s[r][c] *= scale;
                mt = fmaxf(mt, s[r][c]);
            }
#pragma unroll
            for (int w = 1; w < 8; w <<= 1)
                mt = fmaxf(mt, __shfl_xor_sync(0xffffffffu, mt, w));
            float mnew  = fmaxf(m[r], mt);
            float alpha = __expf(m[r] - mnew);
            float lsum  = 0.f;
#pragma unroll
            for (int c = 0; c < 8; c++) {
                float p = __expf(s[r][c] - mnew);
                sP[(4 * ty + r) * PS + 8 * c + tx] = p;
                lsum += p;
            }
#pragma unroll
            for (int w = 1; w < 8; w <<= 1)
                lsum += __shfl_xor_sync(0xffffffffu, lsum, w);
            l[r] = l[r] * alpha + lsum;
            m[r] = mnew;
#pragma unroll
            for (int c = 0; c < 12; c++) o[r][c] *= alpha;
        }
        __syncthreads();

#pragma unroll 2
        for (int j = 0; j < ABN; j++) {
            float pv[4], vv[12];
#pragma unroll
            for (int r = 0; r < 4; r++) pv[r] = sP[(4 * ty + r) * PS + j];
#pragma unroll
            for (int c = 0; c < 12; c++) vv[c] = sV[j * QS + 8 * c + tx];
#pragma unroll
            for (int r = 0; r < 4; r++)
#pragma unroll
                for (int c = 0; c < 12; c++)
                    o[r][c] = fmaf(pv[r], vv[c], o[r][c]);
        }
    }

#pragma unroll
    for (int r = 0; r < 4; r++) {
        float inv = 1.f / l[r];
        size_t rowOff = (size_t)(b * SEQL + q0 + 4 * ty + r) * DIMS + h * HD;
#pragma unroll
        for (int c = 0; c < 12; c++)
            O[rowOff + 8 * c + tx] = o[r][c] * inv;
    }
}

// ---------------------------------------------------------------------------
// Launch
// ---------------------------------------------------------------------------
extern "C" void kernel_launch(void* const* d_in, const int* in_sizes, int n_in,
                              void* d_out, int out_size)
{
    const float* Q_in = (const float*)d_in[0];
    const float* K_in = (const float*)d_in[1];
    const float* V_in = (const float*)d_in[2];
    const float* cq   = (const float*)d_in[3];
    const float* ck   = (const float*)d_in[4];
    const float* Wq   = (const float*)d_in[5];
    const float* Wk   = (const float*)d_in[6];
    const float* Wv   = (const float*)d_in[7];
    const float* Wo   = (const float*)d_in[8];
    float* out = (float*)d_out;

    float *q, *k, *v, *att;
    cudaGetSymbolAddress((void**)&q,   g_q);
    cudaGetSymbolAddress((void**)&k,   g_k);
    cudaGetSymbolAddress((void**)&v,   g_v);
    cudaGetSymbolAddress((void**)&att, g_att);

    cudaFuncSetAttribute(gemm_mma_kernel, cudaFuncAttributeMaxDynamicSharedMemorySize,
                         GEMM_SMEM_BYTES);
    cudaFuncSetAttribute(attn_kernel, cudaFuncAttributeMaxDynamicSharedMemorySize,
                         ATTN_SMEM_BYTES);

    dim3 gemmGrid(NROWS / TM, DIMS / TN);   // 32 x 6

    gemm_mma_kernel<<<gemmGrid, 256, GEMM_SMEM_BYTES>>>(Q_in, Wq, q, NROWS, DIMS, DIMS);
    gemm_mma_kernel<<<gemmGrid, 256, GEMM_SMEM_BYTES>>>(K_in, Wk, k, NROWS, DIMS, DIMS);
    gemm_mma_kernel<<<gemmGrid, 256, GEMM_SMEM_BYTES>>>(V_in, Wv, v, NROWS, DIMS, DIMS);

    {
        int total  = NROWS * HEADS * 48;
        int blocks = (total + 255) / 256;
        rope_kernel<<<blocks, 256>>>(q, cq);
        rope_kernel<<<blocks, 256>>>(k, ck);
    }

    attn_kernel<<<dim3(SEQL / ABM, HEADS, BATCH), 128, ATTN_SMEM_BYTES>>>(q, k, v, att);

    gemm_mma_kernel<<<gemmGrid, 256, GEMM_SMEM_BYTES>>>(att, Wo, out, NROWS, DIMS, DIMS);
}

// round 4
// speedup vs baseline: 3.7644x; 2.9776x over previous
#include <cuda_runtime.h>
#include <math.h>
#include <stdint.h>

#define DIMS   768
#define HEADS  8
#define HD     96
#define SEQL   2048
#define BATCH  2
#define NROWS  (BATCH*SEQL)   // 4096

// ---------------------------------------------------------------------------
// Scratch (static device globals: allocation-free, graph-capture safe)
// ---------------------------------------------------------------------------
__device__ float    g_q  [NROWS*DIMS];
__device__ float    g_k  [NROWS*DIMS];
__device__ float    g_v  [NROWS*DIMS];
__device__ float    g_att[NROWS*DIMS];
__device__ uint32_t g_vt [BATCH*HEADS*HD*SEQL];   // V^T, tf32 bits, [b*8+h][d][t]

// ---------------------------------------------------------------------------
// PTX helpers
// ---------------------------------------------------------------------------
__device__ __forceinline__ uint32_t smem_u32(const void* p) {
    uint32_t a;
    asm("{ .reg .u64 t; cvta.to.shared.u64 t, %1; cvt.u32.u64 %0, t; }" : "=r"(a) : "l"(p));
    return a;
}
__device__ __forceinline__ void cp_async16(uint32_t dst, const void* src) {
    asm volatile("cp.async.cg.shared.global [%0], [%1], 16;" :: "r"(dst), "l"(src));
}
__device__ __forceinline__ void cp_async_commit() { asm volatile("cp.async.commit_group;" ::: "memory"); }
template<int N>
__device__ __forceinline__ void cp_async_wait() { asm volatile("cp.async.wait_group %0;" :: "n"(N) : "memory"); }

__device__ __forceinline__ uint32_t f2tf32(float x) {
    uint32_t u;
    asm("cvt.rna.tf32.f32 %0, %1;" : "=r"(u) : "f"(x));
    return u;
}
__device__ __forceinline__ void mma_tf32(float& c0, float& c1, float& c2, float& c3,
                                         uint32_t a0, uint32_t a1, uint32_t a2, uint32_t a3,
                                         uint32_t b0, uint32_t b1) {
    asm volatile(
        "mma.sync.aligned.m16n8k8.row.col.f32.tf32.tf32.f32 "
        "{%0,%1,%2,%3}, {%4,%5,%6,%7}, {%8,%9}, {%0,%1,%2,%3};"
        : "+f"(c0), "+f"(c1), "+f"(c2), "+f"(c3)
        : "r"(a0), "r"(a1), "r"(a2), "r"(a3), "r"(b0), "r"(b1));
}

// ---------------------------------------------------------------------------
// NT GEMM body via mma.sync tf32 (same as R3, proven).
// ---------------------------------------------------------------------------
#define TM   128
#define TN   128
#define KCH  32
#define PITCH 36
#define STAGE_F (TM * PITCH)
#define GEMM_SMEM_BYTES (4 * STAGE_F * 4)   // 73728 B

__device__ __forceinline__
void gemm_body(const float* __restrict__ A, const float* __restrict__ B,
               float* __restrict__ C, int M, int N, int K, float* smem)
{
    float* sA = smem;
    float* sB = smem + 2 * STAGE_F;

    const int tid  = threadIdx.x;
    const int wid  = tid >> 5;
    const int lane = tid & 31;
    const int grp  = lane >> 2;
    const int thr  = lane & 3;
    const int wm   = (wid & 3) * 32;
    const int wn   = (wid >> 2) * 64;
    const int rowBase = blockIdx.x * TM;
    const int colBase = blockIdx.y * TN;

    const uint32_t sA_u = smem_u32(sA);
    const uint32_t sB_u = smem_u32(sB);

    float acc[2][8][4];
#pragma unroll
    for (int mt = 0; mt < 2; mt++)
#pragma unroll
        for (int nt = 0; nt < 8; nt++)
#pragma unroll
            for (int i = 0; i < 4; i++) acc[mt][nt][i] = 0.f;

    const int nChunks = K / KCH;

#define PREFETCH(ch)                                                            \
    do {                                                                        \
        int _k0 = (ch) * KCH;                                                   \
        uint32_t _dA = sA_u + ((ch) & 1) * STAGE_F * 4;                         \
        uint32_t _dB = sB_u + ((ch) & 1) * STAGE_F * 4;                         \
        _Pragma("unroll")                                                       \
        for (int _it = 0; _it < 4; _it++) {                                     \
            int _idx = tid + _it * 256;                                         \
            int _r = _idx >> 3, _seg = _idx & 7;                                \
            cp_async16(_dA + (_r * PITCH + _seg * 4) * 4,                       \
                       A + (size_t)(rowBase + _r) * K + _k0 + _seg * 4);        \
            cp_async16(_dB + (_r * PITCH + _seg * 4) * 4,                       \
                       B + (size_t)(colBase + _r) * K + _k0 + _seg * 4);        \
        }                                                                       \
        cp_async_commit();                                                      \
    } while (0)

    PREFETCH(0);

    for (int ch = 0; ch < nChunks; ch++) {
        if (ch + 1 < nChunks) { PREFETCH(ch + 1); cp_async_wait<1>(); }
        else                  { cp_async_wait<0>(); }
        __syncthreads();

        const float* cA = sA + (ch & 1) * STAGE_F;
        const float* cB = sB + (ch & 1) * STAGE_F;

#pragma unroll
        for (int ks = 0; ks < 4; ks++) {
            const int kk = ks * 8;
            uint32_t af[2][4];
#pragma unroll
            for (int mt = 0; mt < 2; mt++) {
                int rb = wm + mt * 16 + grp;
                af[mt][0] = f2tf32(cA[(rb    ) * PITCH + kk + thr    ]);
                af[mt][1] = f2tf32(cA[(rb + 8) * PITCH + kk + thr    ]);
                af[mt][2] = f2tf32(cA[(rb    ) * PITCH + kk + thr + 4]);
                af[mt][3] = f2tf32(cA[(rb + 8) * PITCH + kk + thr + 4]);
            }
            uint32_t bf[8][2];
#pragma unroll
            for (int nt = 0; nt < 8; nt++) {
                int cb = wn + nt * 8 + grp;
                bf[nt][0] = f2tf32(cB[cb * PITCH + kk + thr    ]);
                bf[nt][1] = f2tf32(cB[cb * PITCH + kk + thr + 4]);
            }
#pragma unroll
            for (int mt = 0; mt < 2; mt++)
#pragma unroll
                for (int nt = 0; nt < 8; nt++)
                    mma_tf32(acc[mt][nt][0], acc[mt][nt][1],
                             acc[mt][nt][2], acc[mt][nt][3],
                             af[mt][0], af[mt][1], af[mt][2], af[mt][3],
                             bf[nt][0], bf[nt][1]);
        }
        __syncthreads();
    }
#undef PREFETCH

#pragma unroll
    for (int mt = 0; mt < 2; mt++) {
        int r0 = rowBase + wm + mt * 16 + grp;
#pragma unroll
        for (int nt = 0; nt < 8; nt++) {
            int c0 = colBase + wn + nt * 8 + thr * 2;
            float2* p0 = (float2*)(C + (size_t)r0 * N + c0);
            float2* p1 = (float2*)(C + (size_t)(r0 + 8) * N + c0);
            *p0 = make_float2(acc[mt][nt][0], acc[mt][nt][1]);
            *p1 = make_float2(acc[mt][nt][2], acc[mt][nt][3]);
        }
    }
}

// Merged Q/K/V projection: grid.z selects which GEMM.
__global__ __launch_bounds__(256)
void gemm_qkv_kernel(const float* __restrict__ Qin, const float* __restrict__ Kin,
                     const float* __restrict__ Vin, const float* __restrict__ Wq,
                     const float* __restrict__ Wk, const float* __restrict__ Wv,
                     float* __restrict__ q, float* __restrict__ k, float* __restrict__ v)
{
    extern __shared__ float smem[];
    const float *A, *B;
    float* C;
    if      (blockIdx.z == 0) { A = Qin; B = Wq; C = q; }
    else if (blockIdx.z == 1) { A = Kin; B = Wk; C = k; }
    else                      { A = Vin; B = Wv; C = v; }
    gemm_body(A, B, C, NROWS, DIMS, DIMS, smem);
}

__global__ __launch_bounds__(256)
void gemm_mma_kernel(const float* __restrict__ A, const float* __restrict__ B,
                     float* __restrict__ C, int M, int N, int K)
{
    extern __shared__ float smem[];
    gemm_body(A, B, C, M, N, K, smem);
}

// ---------------------------------------------------------------------------
// 3D RoPE; writes results as tf32-rounded fp32 (feeds MMA directly).
// ---------------------------------------------------------------------------
__global__ void rope_kernel(float* __restrict__ x, const float* __restrict__ coords)
{
    const int total = NROWS * HEADS * 48;
    int idx = blockIdx.x * blockDim.x + threadIdx.x;
    if (idx >= total) return;

    int p  = idx % 48;
    int h  = (idx / 48) % HEADS;
    int bl = idx / (48 * HEADS);
    int axis = p >> 4;
    int j    = p & 15;

    float coord = coords[(size_t)bl * 3 + axis];
    float inv = expf(-(float)j * (1.0f / 16.0f) * logf(10000.0f));
    float ang = coord * inv;
    float s, c;
    sincosf(ang, &s, &c);

    float* base = x + (size_t)bl * DIMS + h * HD + axis * 32;
    float x1 = base[j];
    float x2 = base[j + 16];
    base[j]      = __uint_as_float(f2tf32(x1 * c - x2 * s));
    base[j + 16] = __uint_as_float(f2tf32(x1 * s + x2 * c));
}

// ---------------------------------------------------------------------------
// V transpose: v[4096,768] -> vt[(b*8+h)*96+d][2048], stored as tf32 bits.
// 32x32 tiles, 32x8 threads.
// ---------------------------------------------------------------------------
__global__ __launch_bounds__(256)
void transpose_v_kernel(const float* __restrict__ v, uint32_t* __restrict__ vt)
{
    __shared__ float t[32][33];
    const int tx = threadIdx.x & 31;
    const int ty = threadIdx.x >> 5;      // 0..7
    const int c0 = blockIdx.x * 32;       // feature col base (24 tiles, no h straddle)
    const int r0 = blockIdx.y * 32;       // token row base

#pragma unroll
    for (int i = 0; i < 4; i++)
        t[ty + i * 8][tx] = v[(size_t)(r0 + ty + i * 8) * DIMS + c0 + tx];
    __syncthreads();

#pragma unroll
    for (int i = 0; i < 4; i++) {
        int c = c0 + ty + i * 8;          // global feature col
        int h = c / HD, d = c % HD;
        int b = r0 >> 11, tl = r0 & 2047;
        vt[((size_t)(b * HEADS + h) * HD + d) * SEQL + tl + tx] =
            f2tf32(t[tx][ty + i * 8]);
    }
}

// ---------------------------------------------------------------------------
// Flash attention on mma.sync tf32.
// BQ=64, BK=64, 128 threads (4 warps); warp-M=16, warp-N=64.
// sQ/sK: [64][100] tf32 bits (pitch 100 == 4 mod 32 -> conflict-free frags).
// sVT: [96][68] tf32 bits; sP: [64][68] tf32 bits.
// ---------------------------------------------------------------------------
#define BQ 64
#define BK 64
#define QP 100
#define VP 68
#define ATTN_SMEM_U32 (BQ*QP + BK*QP + HD*VP + BQ*VP)       // 23680
#define ATTN_SMEM_BYTES (ATTN_SMEM_U32 * 4)                 // 94720

__global__ __launch_bounds__(128)
void attn_mma_kernel(const float* __restrict__ q, const float* __restrict__ k,
                     const uint32_t* __restrict__ vt, float* __restrict__ O)
{
    extern __shared__ uint32_t smu[];
    uint32_t* sQ  = smu;
    uint32_t* sK  = sQ + BQ * QP;
    uint32_t* sVT = sK + BK * QP;
    uint32_t* sP  = sVT + HD * VP;

    const int tid  = threadIdx.x;
    const int wid  = tid >> 5;
    const int lane = tid & 31;
    const int grp  = lane >> 2;
    const int thr  = lane & 3;
    const int wr   = wid * 16;
    const int q0   = blockIdx.x * BQ;
    const int h    = blockIdx.y;
    const int b    = blockIdx.z;

    const uint32_t sQ_u  = smem_u32(sQ);
    const uint32_t sK_u  = smem_u32(sK);
    const uint32_t sVT_u = smem_u32(sVT);

    const float scale = rsqrtf((float)HD);

    const float*    Qb = q  + ((size_t)b * SEQL + q0) * DIMS + h * HD;
    const float*    Kb = k  + (size_t)b * SEQL * DIMS + h * HD;
    const uint32_t* Vb = vt + (size_t)(b * HEADS + h) * HD * SEQL;

    // Q tile: 64 rows x 24 16B-chunks
#pragma unroll
    for (int i = 0; i < 12; i++) {
        int idx = tid + i * 128;
        int r = idx / 24, c4 = idx % 24;
        cp_async16(sQ_u + (r * QP + c4 * 4) * 4, Qb + (size_t)r * DIMS + c4 * 4);
    }
    cp_async_commit();

    float m0 = -1e30f, m1 = -1e30f, l0 = 0.f, l1 = 0.f;
    float o[12][4];
#pragma unroll
    for (int nt = 0; nt < 12; nt++)
#pragma unroll
        for (int i = 0; i < 4; i++) o[nt][i] = 0.f;

    for (int kb = 0; kb < SEQL / BK; kb++) {
        const int k0 = kb * BK;
        __syncthreads();   // previous iteration's sK/sVT consumers done
#pragma unroll
        for (int i = 0; i < 12; i++) {
            int idx = tid + i * 128;
            int r = idx / 24, c4 = idx % 24;
            cp_async16(sK_u + (r * QP + c4 * 4) * 4,
                       Kb + (size_t)(k0 + r) * DIMS + c4 * 4);
        }
#pragma unroll
        for (int i = 0; i < 12; i++) {
            int idx = tid + i * 128;
            int d = idx / 16, c4 = idx % 16;
            cp_async16(sVT_u + (d * VP + c4 * 4) * 4,
                       Vb + (size_t)d * SEQL + k0 + c4 * 4);
        }
        cp_async_commit();
        cp_async_wait<0>();
        __syncthreads();

        // ---- S = Q K^T (warp: 16 rows x 64 keys) ----
        float s[8][4];
#pragma unroll
        for (int nt = 0; nt < 8; nt++)
#pragma unroll
            for (int i = 0; i < 4; i++) s[nt][i] = 0.f;

#pragma unroll
        for (int ks = 0; ks < 12; ks++) {
            const int kk = ks * 8;
            uint32_t a0 = sQ[(wr + grp    ) * QP + kk + thr    ];
            uint32_t a1 = sQ[(wr + grp + 8) * QP + kk + thr    ];
            uint32_t a2 = sQ[(wr + grp    ) * QP + kk + thr + 4];
            uint32_t a3 = sQ[(wr + grp + 8) * QP + kk + thr + 4];
#pragma unroll
            for (int nt = 0; nt < 8; nt++) {
                uint32_t b0 = sK[(nt * 8 + grp) * QP + kk + thr    ];
                uint32_t b1 = sK[(nt * 8 + grp) * QP + kk + thr + 4];
                mma_tf32(s[nt][0], s[nt][1], s[nt][2], s[nt][3],
                         a0, a1, a2, a3, b0, b1);
            }
        }

        // ---- online softmax (rows grp and grp+8) ----
        float mt0 = -1e30f, mt1 = -1e30f;
#pragma unroll
        for (int nt = 0; nt < 8; nt++) {
#pragma unroll
            for (int i = 0; i < 4; i++) s[nt][i] *= scale;
            mt0 = fmaxf(mt0, fmaxf(s[nt][0], s[nt][1]));
            mt1 = fmaxf(mt1, fmaxf(s[nt][2], s[nt][3]));
        }
        mt0 = fmaxf(mt0, __shfl_xor_sync(0xffffffffu, mt0, 1));
        mt0 = fmaxf(mt0, __shfl_xor_sync(0xffffffffu, mt0, 2));
        mt1 = fmaxf(mt1, __shfl_xor_sync(0xffffffffu, mt1, 1));
        mt1 = fmaxf(mt1, __shfl_xor_sync(0xffffffffu, mt1, 2));

        float mn0 = fmaxf(m0, mt0), mn1 = fmaxf(m1, mt1);
        float al0 = __expf(m0 - mn0), al1 = __expf(m1 - mn1);
        float ls0 = 0.f, ls1 = 0.f;

#pragma unroll
        for (int nt = 0; nt < 8; nt++) {
            float p0 = __expf(s[nt][0] - mn0);
            float p1 = __expf(s[nt][1] - mn0);
            float p2 = __expf(s[nt][2] - mn1);
            float p3 = __expf(s[nt][3] - mn1);
            ls0 += p0 + p1;
            ls1 += p2 + p3;
            uint2* w0 = (uint2*)&sP[(wr + grp    ) * VP + nt * 8 + thr * 2];
            uint2* w1 = (uint2*)&sP[(wr + grp + 8) * VP + nt * 8 + thr * 2];
            *w0 = make_uint2(f2tf32(p0), f2tf32(p1));
            *w1 = make_uint2(f2tf32(p2), f2tf32(p3));
        }
        ls0 += __shfl_xor_sync(0xffffffffu, ls0, 1);
        ls0 += __shfl_xor_sync(0xffffffffu, ls0, 2);
        ls1 += __shfl_xor_sync(0xffffffffu, ls1, 1);
        ls1 += __shfl_xor_sync(0xffffffffu, ls1, 2);

        l0 = l0 * al0 + ls0;  m0 = mn0;
        l1 = l1 * al1 + ls1;  m1 = mn1;
#pragma unroll
        for (int nt = 0; nt < 12; nt++) {
            o[nt][0] *= al0; o[nt][1] *= al0;
            o[nt][2] *= al1; o[nt][3] *= al1;
        }
        __syncwarp();

        // ---- O += P V  (A = P rows of this warp, B = V^T) ----
#pragma unroll
        for (int ks = 0; ks < 8; ks++) {
            const int kk = ks * 8;
            uint32_t a0 = sP[(wr + grp    ) * VP + kk + thr    ];
            uint32_t a1 = sP[(wr + grp + 8) * VP + kk + thr    ];
            uint32_t a2 = sP[(wr + grp    ) * VP + kk + thr + 4];
            uint32_t a3 = sP[(wr + grp + 8) * VP + kk + thr + 4];
#pragma unroll
            for (int nt = 0; nt < 12; nt++) {
                uint32_t b0 = sVT[(nt * 8 + grp) * VP + kk + thr    ];
                uint32_t b1 = sVT[(nt * 8 + grp) * VP + kk + thr + 4];
                mma_tf32(o[nt][0], o[nt][1], o[nt][2], o[nt][3],
                         a0, a1, a2, a3, b0, b1);
            }
        }
    }

    // epilogue
    float inv0 = 1.f / l0, inv1 = 1.f / l1;
    size_t row0 = ((size_t)b * SEQL + q0 + wr + grp    ) * DIMS + h * HD;
    size_t row1 = ((size_t)b * SEQL + q0 + wr + grp + 8) * DIMS + h * HD;
#pragma unroll
    for (int nt = 0; nt < 12; nt++) {
        int c = nt * 8 + thr * 2;
        *(float2*)(O + row0 + c) = make_float2(o[nt][0] * inv0, o[nt][1] * inv0);
        *(float2*)(O + row1 + c) = make_float2(o[nt][2] * inv1, o[nt][3] * inv1);
    }
}

// ---------------------------------------------------------------------------
// Launch
// ---------------------------------------------------------------------------
extern "C" void kernel_launch(void* const* d_in, const int* in_sizes, int n_in,
                              void* d_out, int out_size)
{
    const float* Q_in = (const float*)d_in[0];
    const float* K_in = (const float*)d_in[1];
    const float* V_in = (const float*)d_in[2];
    const float* cq   = (const float*)d_in[3];
    const float* ck   = (const float*)d_in[4];
    const float* Wq   = (const float*)d_in[5];
    const float* Wk   = (const float*)d_in[6];
    const float* Wv   = (const float*)d_in[7];
    const float* Wo   = (const float*)d_in[8];
    float* out = (float*)d_out;

    float *q, *k, *v, *att;
    uint32_t* vt;
    cudaGetSymbolAddress((void**)&q,   g_q);
    cudaGetSymbolAddress((void**)&k,   g_k);
    cudaGetSymbolAddress((void**)&v,   g_v);
    cudaGetSymbolAddress((void**)&att, g_att);
    cudaGetSymbolAddress((void**)&vt,  g_vt);

    cudaFuncSetAttribute(gemm_qkv_kernel, cudaFuncAttributeMaxDynamicSharedMemorySize,
                         GEMM_SMEM_BYTES);
    cudaFuncSetAttribute(gemm_mma_kernel, cudaFuncAttributeMaxDynamicSharedMemorySize,
                         GEMM_SMEM_BYTES);
    cudaFuncSetAttribute(attn_mma_kernel, cudaFuncAttributeMaxDynamicSharedMemorySize,
                         ATTN_SMEM_BYTES);

    // fused Q/K/V projections
    gemm_qkv_kernel<<<dim3(NROWS / TM, DIMS / TN, 3), 256, GEMM_SMEM_BYTES>>>(
        Q_in, K_in, V_in, Wq, Wk, Wv, q, k, v);

    // RoPE (writes tf32-rounded) + V transpose (writes tf32 bits)
    {
        int total  = NROWS * HEADS * 48;
        int blocks = (total + 255) / 256;
        rope_kernel<<<blocks, 256>>>(q, cq);
        rope_kernel<<<blocks, 256>>>(k, ck);
    }
    transpose_v_kernel<<<dim3(DIMS / 32, NROWS / 32), 256>>>(v, vt);

    // tensor-core flash attention
    attn_mma_kernel<<<dim3(SEQL / BQ, HEADS, BATCH), 128, ATTN_SMEM_BYTES>>>(q, k, vt, att);

    // output projection
    gemm_mma_kernel<<<dim3(NROWS / TM, DIMS / TN), 256, GEMM_SMEM_BYTES>>>(
        att, Wo, out, NROWS, DIMS, DIMS);
}